// round 8
// baseline (speedup 1.0000x reference)
#include <cuda_runtime.h>

#define E_NUM 8192
#define D 64
#define S1_BLOCKS 1184
#define EVB 32                      // events per block (stage-2 kernel)
#define EV_BLOCKS (E_NUM / EVB)     // 256
#define TS 36                       // tile row stride (floats), %4==0 for LDS.128

typedef unsigned long long ull;

// ---------------- scratch (no allocs allowed) ----------------
__device__ float g_zero[2 * E_NUM + D + E_NUM * D];
#define g_P      (g_zero)                    // [E_NUM] segsum of max(x,0)
#define g_M      (g_zero + E_NUM)            // [E_NUM] segsum of max(-x,0)
#define g_gsum   (g_zero + 2 * E_NUM)        // [D]
#define g_pooled (g_zero + 2 * E_NUM + D)    // [E_NUM*D] generic-path pooled

__device__ float g_u[D], g_v[D];    // r1w0^T relu(v+), r1w0^T relu(v-)
__device__ int   g_flag;            // 1 => phi1 biases nonzero -> generic path
__device__ int   g_cnt;             // last-block ticket (self-resetting)

// packed f32x2 fma: d = a*b + d   (FFMA2 — only reachable via PTX)
__device__ __forceinline__ void ffma2(ull& d, ull a, ull b)
{
    asm("fma.rn.f32x2 %0, %1, %2, %0;" : "+l"(d) : "l"(a), "l"(b));
}
__device__ __forceinline__ ull dup2(float w)
{
    ull d; asm("mov.b64 %0, {%1, %1};" : "=l"(d) : "f"(w)); return d;
}
__device__ __forceinline__ float2 unpk(ull d)
{
    float2 r; asm("mov.b64 {%0, %1}, %2;" : "=f"(r.x), "=f"(r.y) : "l"(d)); return r;
}

// ---------------- K1: stage-1 phi + segment pooling (+ prep fused) ----------------
__global__ void __launch_bounds__(256) k_stage1(
    const float* __restrict__ x, const int* __restrict__ seg, int n,
    const float* __restrict__ w0, const float* __restrict__ b0,
    const float* __restrict__ W1, const float* __restrict__ b1,
    const float* __restrict__ r1w0)
{
    const int tid = threadIdx.x;
    __shared__ float scp[D], scm[D];

    int nz = 0;
    if (tid < D) nz = (b0[tid] != 0.f) || (b1[tid] != 0.f);
    const int anyb = __syncthreads_or(nz);

    if (blockIdx.x == 0) {
        if (tid == 0) g_flag = anyb;
        if (tid < D) {
            float vp = 0.f, vn = 0.f;
            #pragma unroll
            for (int j = 0; j < D; j++) {
                float w   = w0[j];
                float col = W1[j * D + tid];
                vp += fmaxf(w, 0.f)  * col;
                vn += fmaxf(-w, 0.f) * col;
            }
            scp[tid] = fmaxf(vp, 0.f);
            scm[tid] = fmaxf(vn, 0.f);
        }
        __syncthreads();
        if (tid < D) {
            float u = 0.f, v = 0.f;
            #pragma unroll
            for (int j = 0; j < D; j++) {
                float w = r1w0[j * D + tid];
                u += scp[j] * w;
                v += scm[j] * w;
            }
            g_u[tid] = u;
            g_v[tid] = v;
        }
    }

    if (!anyb) {
        // ---- fast path: two scalar segment sums, HBM-bound ----
        const int lane   = tid & 31;
        const int warp   = (blockIdx.x * blockDim.x + tid) >> 5;
        const int nwarps = (gridDim.x * blockDim.x) >> 5;
        const int G      = n >> 2;
        const int gpw    = (G + nwarps - 1) / nwarps;

        const long long gbase = (long long)warp * gpw;
        const long long gend0 = gbase + gpw;
        const long long gend  = gend0 < (long long)G ? gend0 : (long long)G;

        const float4* x4 = (const float4*)x;
        const int4*   s4 = (const int4*)seg;

        int   cur = -1;
        float aP = 0.f, aM = 0.f;

        for (long long g = gbase + lane; g < gend; g += 32) {
            float4 xv = x4[g];
            int4   sv = s4[g];
            int   ss[4] = {sv.x, sv.y, sv.z, sv.w};
            float xs[4] = {xv.x, xv.y, xv.z, xv.w};
            #pragma unroll
            for (int u = 0; u < 4; u++) {
                int s = ss[u];
                if (s != cur) {
                    if (cur >= 0) { atomicAdd(&g_P[cur], aP); atomicAdd(&g_M[cur], aM); }
                    cur = s; aP = 0.f; aM = 0.f;
                }
                aP += fmaxf(xs[u],  0.f);
                aM += fmaxf(-xs[u], 0.f);
            }
        }
        if (cur >= 0) { atomicAdd(&g_P[cur], aP); atomicAdd(&g_M[cur], aM); }

        if (warp == 0 && lane == 0) {
            for (int i = G * 4; i < n; i++) {
                float xv = x[i]; int s = seg[i];
                atomicAdd(&g_P[s], fmaxf(xv,  0.f));
                atomicAdd(&g_M[s], fmaxf(-xv, 0.f));
            }
        }
    } else {
        // ---- generic fallback (never taken for this problem's inputs) ----
        __shared__ float sw0[D], sb0[D], sW1[D * D], sb1[D];
        for (int i = tid; i < D; i += blockDim.x) {
            sw0[i] = w0[i]; sb0[i] = b0[i]; sb1[i] = b1[i];
        }
        for (int i = tid; i < D * D; i += blockDim.x) sW1[i] = W1[i];
        __syncthreads();

        const int stride = gridDim.x * blockDim.x;
        for (int i = blockIdx.x * blockDim.x + tid; i < n; i += stride) {
            float xv = x[i];
            int   e  = seg[i];
            float h1[D];
            #pragma unroll
            for (int j = 0; j < D; j++) h1[j] = fmaxf(xv * sw0[j] + sb0[j], 0.f);
            #pragma unroll 2
            for (int k = 0; k < D; k++) {
                float acc = sb1[k];
                #pragma unroll
                for (int j = 0; j < D; j++) acc += h1[j] * sW1[j * D + k];
                atomicAdd(&g_pooled[e * D + k], fmaxf(acc, 0.f));
            }
        }
    }
}

// ---------------- K2: event MLP, 4f x 4e per thread, f32x2, dbl-buffered W ----------------
__global__ void __launch_bounds__(128, 4) k_events_final(
    const float* __restrict__ r1w0, const float* __restrict__ r1b0,
    const float* __restrict__ r1w1, const float* __restrict__ r1b1,
    const float* __restrict__ o1w,  const float* __restrict__ o1b,
    const float* __restrict__ p2w0, const float* __restrict__ p2b0,
    const float* __restrict__ p2w1, const float* __restrict__ p2b1,
    const float* __restrict__ r2w0, const float* __restrict__ r2b0,
    const float* __restrict__ r2w1, const float* __restrict__ r2b1,
    const float* __restrict__ o2w,  const float* __restrict__ o2b,
    float* __restrict__ out)
{
    __shared__ __align__(16) float shW[2][D * D];   // double-buffered weights
    __shared__ __align__(16) float sB[5 * D];       // all biases
    __shared__ __align__(16) float tile[D * TS];    // [feat][event], EVB events
    __shared__ float sP[EVB], sM[EVB];
    __shared__ float sf0[D], sf1[D], sf2[D];
    __shared__ int   s_last;

    const int tid  = threadIdx.x;
    const int e0   = blockIdx.x * EVB;
    const int flag = g_flag;
    const int eg   = tid & 7;        // event group: events 4eg..4eg+3
    const int kb   = (tid >> 3) * 4; // feature base: feats kb..kb+3

    const float* Ws[5];
    const float* Bs[5];
    int NL;
    if (!flag) {
        Ws[0] = r1w1; Bs[0] = r1b1;
        Ws[1] = o1w;  Bs[1] = o1b;
        Ws[2] = p2w0; Bs[2] = p2b0;
        Ws[3] = p2w1; Bs[3] = p2b1;
        Ws[4] = p2w1; Bs[4] = p2b1;   // unused
        NL = 4;
    } else {
        Ws[0] = r1w0; Bs[0] = r1b0;
        Ws[1] = r1w1; Bs[1] = r1b1;
        Ws[2] = o1w;  Bs[2] = o1b;
        Ws[3] = p2w0; Bs[3] = p2b0;
        Ws[4] = p2w1; Bs[4] = p2b1;
        NL = 5;
    }

    // preload all biases + layer-0 weights
    for (int i = tid; i < NL * D; i += 128) sB[i] = Bs[i >> 6][i & 63];
    {
        const float4* src = (const float4*)Ws[0];
        float4* dst = (float4*)shW[0];
        #pragma unroll
        for (int s = 0; s < 8; s++) dst[tid + s * 128] = src[tid + s * 128];
    }

    // build input tile [feat][event]
    if (!flag) {
        if (tid < EVB)            sP[tid]        = g_P[e0 + tid];
        else if (tid < 2 * EVB)   sM[tid - EVB]  = g_M[e0 + tid - EVB];
        __syncthreads();
        float p0 = sP[4*eg], p1 = sP[4*eg+1], p2 = sP[4*eg+2], p3 = sP[4*eg+3];
        float m0 = sM[4*eg], m1 = sM[4*eg+1], m2 = sM[4*eg+2], m3 = sM[4*eg+3];
        #pragma unroll
        for (int t = 0; t < 4; t++) {
            int k = kb + t;
            float u = g_u[k], v = g_v[k], b = r1b0[k];
            float4 h;
            h.x = fmaxf(p0 * u + m0 * v + b, 0.f);
            h.y = fmaxf(p1 * u + m1 * v + b, 0.f);
            h.z = fmaxf(p2 * u + m2 * v + b, 0.f);
            h.w = fmaxf(p3 * u + m3 * v + b, 0.f);
            *(float4*)&tile[k * TS + 4 * eg] = h;
        }
    } else {
        for (int i = tid; i < D * EVB; i += 128) {
            int j = i >> 5, e = i & 31;
            tile[j * TS + e] = g_pooled[(e0 + e) * D + j];
        }
    }
    __syncthreads();   // tile + W0 + biases ready

    for (int L = 0; L < NL; L++) {
        const float* cw = shW[L & 1];

        // prefetch next layer's weights into the other buffer (overlaps compute)
        if (L + 1 < NL) {
            const float4* src = (const float4*)Ws[L + 1];
            float4* dst = (float4*)shW[(L + 1) & 1];
            #pragma unroll
            for (int s = 0; s < 8; s++) dst[tid + s * 128] = src[tid + s * 128];
        }

        float4 bv = *(const float4*)&sB[L * D + kb];
        ull a00 = dup2(bv.x), a01 = a00;
        ull a10 = dup2(bv.y), a11 = a10;
        ull a20 = dup2(bv.z), a21 = a20;
        ull a30 = dup2(bv.w), a31 = a30;

        #pragma unroll 8
        for (int j = 0; j < D; j++) {
            ulonglong2 av = *(const ulonglong2*)&tile[j * TS + 4 * eg];
            float4 wv = *(const float4*)&cw[j * D + kb];
            ull w0 = dup2(wv.x), w1 = dup2(wv.y), w2 = dup2(wv.z), w3 = dup2(wv.w);
            ffma2(a00, av.x, w0); ffma2(a01, av.y, w0);
            ffma2(a10, av.x, w1); ffma2(a11, av.y, w1);
            ffma2(a20, av.x, w2); ffma2(a21, av.y, w2);
            ffma2(a30, av.x, w3); ffma2(a31, av.y, w3);
        }
        __syncthreads();   // tile reads done; next-W STS drained

        // relu + store transposed
        {
            float2 lo, hi; float4 o;
            lo = unpk(a00); hi = unpk(a01);
            o = make_float4(fmaxf(lo.x,0.f), fmaxf(lo.y,0.f), fmaxf(hi.x,0.f), fmaxf(hi.y,0.f));
            *(float4*)&tile[(kb + 0) * TS + 4 * eg] = o;
            lo = unpk(a10); hi = unpk(a11);
            o = make_float4(fmaxf(lo.x,0.f), fmaxf(lo.y,0.f), fmaxf(hi.x,0.f), fmaxf(hi.y,0.f));
            *(float4*)&tile[(kb + 1) * TS + 4 * eg] = o;
            lo = unpk(a20); hi = unpk(a21);
            o = make_float4(fmaxf(lo.x,0.f), fmaxf(lo.y,0.f), fmaxf(hi.x,0.f), fmaxf(hi.y,0.f));
            *(float4*)&tile[(kb + 2) * TS + 4 * eg] = o;
            lo = unpk(a30); hi = unpk(a31);
            o = make_float4(fmaxf(lo.x,0.f), fmaxf(lo.y,0.f), fmaxf(hi.x,0.f), fmaxf(hi.y,0.f));
            *(float4*)&tile[(kb + 3) * TS + 4 * eg] = o;
        }
        __syncthreads();
    }

    // sum this block's events -> atomic into g_gsum
    if (tid < D) {
        float s = 0.f;
        #pragma unroll
        for (int e = 0; e < EVB; e++) s += tile[tid * TS + e];
        atomicAdd(&g_gsum[tid], s);
    }

    // ---- last-block ticket: rho2 + output ----
    __threadfence();
    __syncthreads();
    if (tid == 0) {
        int old = atomicAdd(&g_cnt, 1);
        s_last = (old == (int)gridDim.x - 1);
    }
    __syncthreads();

    if (s_last) {
        if (tid < D) sf0[tid] = __ldcg(&g_gsum[tid]);
        __syncthreads();
        if (tid < D) {
            float a = r2b0[tid];
            #pragma unroll
            for (int j = 0; j < D; j++) a += sf0[j] * r2w0[j * D + tid];
            sf1[tid] = fmaxf(a, 0.f);
        }
        __syncthreads();
        if (tid < D) {
            float a = r2b1[tid];
            #pragma unroll
            for (int j = 0; j < D; j++) a += sf1[j] * r2w1[j * D + tid];
            sf2[tid] = fmaxf(a, 0.f);
        }
        __syncthreads();
        if (tid < 10) {
            float a = o2b[tid];
            #pragma unroll
            for (int j = 0; j < D; j++) a += sf2[j] * o2w[j * 10 + tid];
            out[tid] = a;
        }
        if (tid == 0) g_cnt = 0;   // self-reset for next replay
    }
}

// ---------------- launch ----------------
extern "C" void kernel_launch(void* const* d_in, const int* in_sizes, int n_in,
                              void* d_out, int out_size)
{
    const float* x    = (const float*)d_in[0];
    const int*   seg  = (const int*)  d_in[1];
    const float* p1w0 = (const float*)d_in[2];
    const float* p1b0 = (const float*)d_in[3];
    const float* p1w1 = (const float*)d_in[4];
    const float* p1b1 = (const float*)d_in[5];
    const float* r1w0 = (const float*)d_in[6];
    const float* r1b0 = (const float*)d_in[7];
    const float* r1w1 = (const float*)d_in[8];
    const float* r1b1 = (const float*)d_in[9];
    const float* o1w  = (const float*)d_in[10];
    const float* o1b  = (const float*)d_in[11];
    const float* p2w0 = (const float*)d_in[12];
    const float* p2b0 = (const float*)d_in[13];
    const float* p2w1 = (const float*)d_in[14];
    const float* p2b1 = (const float*)d_in[15];
    const float* r2w0 = (const float*)d_in[16];
    const float* r2b0 = (const float*)d_in[17];
    const float* r2w1 = (const float*)d_in[18];
    const float* r2b1 = (const float*)d_in[19];
    const float* o2w  = (const float*)d_in[20];
    const float* o2b  = (const float*)d_in[21];
    const int n = in_sizes[0];

    void* zp = nullptr;
    cudaGetSymbolAddress(&zp, g_zero);
    cudaMemsetAsync(zp, 0, sizeof(float) * (2 * E_NUM + D + E_NUM * D));

    k_stage1<<<S1_BLOCKS, 256>>>(x, seg, n, p1w0, p1b0, p1w1, p1b1, r1w0);
    k_events_final<<<EV_BLOCKS, 128>>>(r1w0, r1b0, r1w1, r1b1, o1w, o1b,
                                       p2w0, p2b0, p2w1, p2b1,
                                       r2w0, r2b0, r2w1, r2b1,
                                       o2w, o2b, (float*)d_out);
}

// round 10
// speedup vs baseline: 1.2806x; 1.2806x over previous
#include <cuda_runtime.h>

#define E_NUM 8192
#define D 64
#define S1_BLOCKS 592
#define EVW 8                       // events per warp
#define WPB 4                       // warps per block
#define EVB (EVW * WPB)             // 32 events per block
#define EV_BLOCKS (E_NUM / EVB)     // 256
#define WST 66                      // sW row stride in ull (16B-aligned rows)

typedef unsigned long long ull;

// ---------------- scratch (no allocs allowed) ----------------
__device__ float g_zero[2 * E_NUM + D + E_NUM * D];
#define g_P      (g_zero)                    // [E_NUM] segsum of max(x,0)
#define g_M      (g_zero + E_NUM)            // [E_NUM] segsum of max(-x,0)
#define g_gsum   (g_zero + 2 * E_NUM)        // [D]
#define g_pooled (g_zero + 2 * E_NUM + D)    // [E_NUM*D] generic-path pooled

__device__ float g_u[D], g_v[D];    // r1w0^T relu(v+), r1w0^T relu(v-)
__device__ int   g_flag;            // 1 => phi1 biases nonzero -> generic path
__device__ int   g_cnt;             // last-block ticket (self-resetting)

// ---- packed f32x2 helpers (FFMA2 path, PTX-only) ----
__device__ __forceinline__ void ffma2(ull& d, ull a, ull b)
{
    asm("fma.rn.f32x2 %0, %1, %2, %0;" : "+l"(d) : "l"(a), "l"(b));
}
__device__ __forceinline__ ull dup2(float w)
{
    ull d; asm("mov.b64 %0, {%1, %1};" : "=l"(d) : "f"(w)); return d;
}
__device__ __forceinline__ ull pack2(float lo, float hi)
{
    ull d; asm("mov.b64 %0, {%1, %2};" : "=l"(d) : "f"(lo), "f"(hi)); return d;
}
__device__ __forceinline__ void unpk2(ull d, float& lo, float& hi)
{
    asm("mov.b64 {%0, %1}, %2;" : "=f"(lo), "=f"(hi) : "l"(d));
}
__device__ __forceinline__ ull relu2(ull a)
{
    float lo, hi; unpk2(a, lo, hi);
    return pack2(fmaxf(lo, 0.f), fmaxf(hi, 0.f));
}

// ---------------- K1: stage-1 phi + segment pooling (+ prep fused) ----------------
__global__ void __launch_bounds__(256) k_stage1(
    const float* __restrict__ x, const int* __restrict__ seg, int n,
    const float* __restrict__ w0, const float* __restrict__ b0,
    const float* __restrict__ W1, const float* __restrict__ b1,
    const float* __restrict__ r1w0)
{
    const int tid = threadIdx.x;
    __shared__ float scp[D], scm[D];

    int nz = 0;
    if (tid < D) nz = (b0[tid] != 0.f) || (b1[tid] != 0.f);
    const int anyb = __syncthreads_or(nz);

    if (blockIdx.x == 0) {
        if (tid == 0) g_flag = anyb;
        if (tid < D) {
            float vp = 0.f, vn = 0.f;
            #pragma unroll
            for (int j = 0; j < D; j++) {
                float w   = w0[j];
                float col = W1[j * D + tid];
                vp += fmaxf(w, 0.f)  * col;
                vn += fmaxf(-w, 0.f) * col;
            }
            scp[tid] = fmaxf(vp, 0.f);
            scm[tid] = fmaxf(vn, 0.f);
        }
        __syncthreads();
        if (tid < D) {
            float u = 0.f, v = 0.f;
            #pragma unroll
            for (int j = 0; j < D; j++) {
                float w = r1w0[j * D + tid];
                u += scp[j] * w;
                v += scm[j] * w;
            }
            g_u[tid] = u;
            g_v[tid] = v;
        }
    }

    if (!anyb) {
        // ---- fast path: two scalar segment sums, HBM-bound ----
        const int lane   = tid & 31;
        const int warp   = (blockIdx.x * blockDim.x + tid) >> 5;
        const int nwarps = (gridDim.x * blockDim.x) >> 5;
        const int G      = n >> 2;
        const int gpw    = (G + nwarps - 1) / nwarps;

        const long long gbase = (long long)warp * gpw;
        const long long gend0 = gbase + gpw;
        const long long gend  = gend0 < (long long)G ? gend0 : (long long)G;

        const float4* x4 = (const float4*)x;
        const int4*   s4 = (const int4*)seg;

        int   cur = -1;
        float aP = 0.f, aM = 0.f;

        for (long long g = gbase + lane; g < gend; g += 32) {
            float4 xv = x4[g];
            int4   sv = s4[g];
            int   ss[4] = {sv.x, sv.y, sv.z, sv.w};
            float xs[4] = {xv.x, xv.y, xv.z, xv.w};
            #pragma unroll
            for (int u = 0; u < 4; u++) {
                int s = ss[u];
                if (s != cur) {
                    if (cur >= 0) { atomicAdd(&g_P[cur], aP); atomicAdd(&g_M[cur], aM); }
                    cur = s; aP = 0.f; aM = 0.f;
                }
                aP += fmaxf(xs[u],  0.f);
                aM += fmaxf(-xs[u], 0.f);
            }
        }
        if (cur >= 0) { atomicAdd(&g_P[cur], aP); atomicAdd(&g_M[cur], aM); }

        if (warp == 0 && lane == 0) {
            for (int i = G * 4; i < n; i++) {
                float xv = x[i]; int s = seg[i];
                atomicAdd(&g_P[s], fmaxf(xv,  0.f));
                atomicAdd(&g_M[s], fmaxf(-xv, 0.f));
            }
        }
    } else {
        // ---- generic fallback (never taken for this problem's inputs) ----
        __shared__ float sw0[D], sb0[D], sW1[D * D], sb1[D];
        for (int i = tid; i < D; i += blockDim.x) {
            sw0[i] = w0[i]; sb0[i] = b0[i]; sb1[i] = b1[i];
        }
        for (int i = tid; i < D * D; i += blockDim.x) sW1[i] = W1[i];
        __syncthreads();

        const int stride = gridDim.x * blockDim.x;
        for (int i = blockIdx.x * blockDim.x + tid; i < n; i += stride) {
            float xv = x[i];
            int   e  = seg[i];
            float h1[D];
            #pragma unroll
            for (int j = 0; j < D; j++) h1[j] = fmaxf(xv * sw0[j] + sb0[j], 0.f);
            #pragma unroll 2
            for (int k = 0; k < D; k++) {
                float acc = sb1[k];
                #pragma unroll
                for (int j = 0; j < D; j++) acc += h1[j] * sW1[j * D + k];
                atomicAdd(&g_pooled[e * D + k], fmaxf(acc, 0.f));
            }
        }
    }
}

// load one 64x64 layer into shared, transposed+packed: sW[k2*WST + j] = (W[j][2k2], W[j][2k2+1])
__device__ __forceinline__ void loadW(ull* __restrict__ dst,
                                      const float* __restrict__ src, int tid)
{
    #pragma unroll
    for (int s = 0; s < 16; s++) {
        int i  = tid + s * 128;      // 0..2047
        int j  = i >> 5;
        int k2 = i & 31;
        float2 w = *(const float2*)&src[j * D + 2 * k2];
        dst[k2 * WST + j] = pack2(w.x, w.y);
    }
}

// ---------------- K2: warp-autonomous event MLP + global sum + final ----------------
__global__ void __launch_bounds__(128) k_events_final(
    const float* __restrict__ r1w0, const float* __restrict__ r1b0,
    const float* __restrict__ r1w1, const float* __restrict__ r1b1,
    const float* __restrict__ o1w,  const float* __restrict__ o1b,
    const float* __restrict__ p2w0, const float* __restrict__ p2b0,
    const float* __restrict__ p2w1, const float* __restrict__ p2b1,
    const float* __restrict__ r2w0, const float* __restrict__ r2b0,
    const float* __restrict__ r2w1, const float* __restrict__ r2b1,
    const float* __restrict__ o2w,  const float* __restrict__ o2b,
    float* __restrict__ out)
{
    __shared__ __align__(16) ull  sW[2][32 * WST];   // double-buffered transposed weights
    __shared__ __align__(16) ull  tiles[WPB][4 * D]; // per-warp: [pair][feat] f32x2
    __shared__ float wsum[WPB][D];
    __shared__ float sf0[D], sf1[D], sf2[D];
    __shared__ int   s_last;

    const int tid  = threadIdx.x;
    const int wid  = tid >> 5;
    const int lane = tid & 31;
    const int f0   = 2 * lane;        // this lane's two feature columns
    const int e0   = blockIdx.x * EVB + wid * EVW;
    const int flag = g_flag;

    const float* Ws[5];
    const float* Bs[5];
    int NL;
    if (!flag) {
        Ws[0] = r1w1; Bs[0] = r1b1;
        Ws[1] = o1w;  Bs[1] = o1b;
        Ws[2] = p2w0; Bs[2] = p2b0;
        Ws[3] = p2w1; Bs[3] = p2b1;
        NL = 4;
    } else {
        Ws[0] = r1w0; Bs[0] = r1b0;
        Ws[1] = r1w1; Bs[1] = r1b1;
        Ws[2] = o1w;  Bs[2] = o1b;
        Ws[3] = p2w0; Bs[3] = p2b0;
        Ws[4] = p2w1; Bs[4] = p2b1;
        NL = 5;
    }

    // layer-0 weights into buffer 0
    loadW(sW[0], Ws[0], tid);

    // build this warp's input tile [pair][feat] (warp-local)
    ull* tile = tiles[wid];
    if (!flag) {
        float4 Pa = *(const float4*)&g_P[e0];
        float4 Pb = *(const float4*)&g_P[e0 + 4];
        float4 Ma = *(const float4*)&g_M[e0];
        float4 Mb = *(const float4*)&g_M[e0 + 4];
        float u0 = g_u[f0], u1 = g_u[f0 + 1];
        float v0 = g_v[f0], v1 = g_v[f0 + 1];
        float b0f = r1b0[f0], b1f = r1b0[f0 + 1];
        float Pv[8] = {Pa.x, Pa.y, Pa.z, Pa.w, Pb.x, Pb.y, Pb.z, Pb.w};
        float Mv[8] = {Ma.x, Ma.y, Ma.z, Ma.w, Mb.x, Mb.y, Mb.z, Mb.w};
        #pragma unroll
        for (int p = 0; p < 4; p++) {
            float lo0 = fmaxf(Pv[2*p]   * u0 + Mv[2*p]   * v0 + b0f, 0.f);
            float hi0 = fmaxf(Pv[2*p+1] * u0 + Mv[2*p+1] * v0 + b0f, 0.f);
            float lo1 = fmaxf(Pv[2*p]   * u1 + Mv[2*p]   * v1 + b1f, 0.f);
            float hi1 = fmaxf(Pv[2*p+1] * u1 + Mv[2*p+1] * v1 + b1f, 0.f);
            ulonglong2 st; st.x = pack2(lo0, hi0); st.y = pack2(lo1, hi1);
            *(ulonglong2*)&tile[p * D + f0] = st;
        }
    } else {
        #pragma unroll
        for (int p = 0; p < 4; p++) {
            ulonglong2 st;
            st.x = pack2(g_pooled[(e0 + 2*p) * D + f0],
                         g_pooled[(e0 + 2*p + 1) * D + f0]);
            st.y = pack2(g_pooled[(e0 + 2*p) * D + f0 + 1],
                         g_pooled[(e0 + 2*p + 1) * D + f0 + 1]);
            *(ulonglong2*)&tile[p * D + f0] = st;
        }
    }

    for (int L = 0; L < NL; L++) {
        __syncthreads();                       // weight buffer L ready / other buffer free
        const ull* cw = sW[L & 1] + lane * WST;
        if (L + 1 < NL) loadW(sW[(L + 1) & 1], Ws[L + 1], tid);  // prefetch under compute

        float bf0 = Bs[L][f0], bf1 = Bs[L][f0 + 1];
        ull a00 = dup2(bf0), a01 = a00, a02 = a00, a03 = a00;   // feat f0, pairs 0..3
        ull a10 = dup2(bf1), a11 = a10, a12 = a10, a13 = a10;   // feat f0+1

        #pragma unroll 8
        for (int j = 0; j < D; j += 2) {
            ulonglong2 lw = *(const ulonglong2*)&cw[j];
            float wja, wjb, wka, wkb;
            unpk2(lw.x, wja, wjb);             // W[j][f0], W[j][f0+1]
            unpk2(lw.y, wka, wkb);             // W[j+1][f0], W[j+1][f0+1]
            ull wj0 = dup2(wja), wj1 = dup2(wjb);
            ull wk0 = dup2(wka), wk1 = dup2(wkb);
            ulonglong2 t0 = *(const ulonglong2*)&tile[0 * D + j];
            ulonglong2 t1 = *(const ulonglong2*)&tile[1 * D + j];
            ulonglong2 t2 = *(const ulonglong2*)&tile[2 * D + j];
            ulonglong2 t3 = *(const ulonglong2*)&tile[3 * D + j];
            ffma2(a00, t0.x, wj0); ffma2(a01, t1.x, wj0);
            ffma2(a02, t2.x, wj0); ffma2(a03, t3.x, wj0);
            ffma2(a10, t0.x, wj1); ffma2(a11, t1.x, wj1);
            ffma2(a12, t2.x, wj1); ffma2(a13, t3.x, wj1);
            ffma2(a00, t0.y, wk0); ffma2(a01, t1.y, wk0);
            ffma2(a02, t2.y, wk0); ffma2(a03, t3.y, wk0);
            ffma2(a10, t0.y, wk1); ffma2(a11, t1.y, wk1);
            ffma2(a12, t2.y, wk1); ffma2(a13, t3.y, wk1);
        }

        if (L < NL - 1) {
            __syncwarp();                      // all lanes done reading tile
            ulonglong2 s0; s0.x = relu2(a00); s0.y = relu2(a10);
            ulonglong2 s1; s1.x = relu2(a01); s1.y = relu2(a11);
            ulonglong2 s2; s2.x = relu2(a02); s2.y = relu2(a12);
            ulonglong2 s3; s3.x = relu2(a03); s3.y = relu2(a13);
            *(ulonglong2*)&tile[0 * D + f0] = s0;
            *(ulonglong2*)&tile[1 * D + f0] = s1;
            *(ulonglong2*)&tile[2 * D + f0] = s2;
            *(ulonglong2*)&tile[3 * D + f0] = s3;
            __syncwarp();
        } else {
            // last layer: relu + sum this warp's 8 events per feature
            float lo, hi, sA = 0.f, sB = 0.f;
            unpk2(a00, lo, hi); sA += fmaxf(lo,0.f) + fmaxf(hi,0.f);
            unpk2(a01, lo, hi); sA += fmaxf(lo,0.f) + fmaxf(hi,0.f);
            unpk2(a02, lo, hi); sA += fmaxf(lo,0.f) + fmaxf(hi,0.f);
            unpk2(a03, lo, hi); sA += fmaxf(lo,0.f) + fmaxf(hi,0.f);
            unpk2(a10, lo, hi); sB += fmaxf(lo,0.f) + fmaxf(hi,0.f);
            unpk2(a11, lo, hi); sB += fmaxf(lo,0.f) + fmaxf(hi,0.f);
            unpk2(a12, lo, hi); sB += fmaxf(lo,0.f) + fmaxf(hi,0.f);
            unpk2(a13, lo, hi); sB += fmaxf(lo,0.f) + fmaxf(hi,0.f);
            wsum[wid][f0]     = sA;
            wsum[wid][f0 + 1] = sB;
        }
    }

    __syncthreads();
    if (tid < D) {
        float tot = wsum[0][tid] + wsum[1][tid] + wsum[2][tid] + wsum[3][tid];
        atomicAdd(&g_gsum[tid], tot);
    }

    // ---- last-block ticket: rho2 + output ----
    __threadfence();
    __syncthreads();
    if (tid == 0) {
        int old = atomicAdd(&g_cnt, 1);
        s_last = (old == (int)gridDim.x - 1);
    }
    __syncthreads();

    if (s_last) {
        if (tid < D) sf0[tid] = __ldcg(&g_gsum[tid]);
        __syncthreads();
        if (tid < D) {
            float a = r2b0[tid];
            #pragma unroll
            for (int j = 0; j < D; j++) a += sf0[j] * r2w0[j * D + tid];
            sf1[tid] = fmaxf(a, 0.f);
        }
        __syncthreads();
        if (tid < D) {
            float a = r2b1[tid];
            #pragma unroll
            for (int j = 0; j < D; j++) a += sf1[j] * r2w1[j * D + tid];
            sf2[tid] = fmaxf(a, 0.f);
        }
        __syncthreads();
        if (tid < 10) {
            float a = o2b[tid];
            #pragma unroll
            for (int j = 0; j < D; j++) a += sf2[j] * o2w[j * 10 + tid];
            out[tid] = a;
        }
        if (tid == 0) g_cnt = 0;   // self-reset for next replay
    }
}

// ---------------- launch ----------------
extern "C" void kernel_launch(void* const* d_in, const int* in_sizes, int n_in,
                              void* d_out, int out_size)
{
    const float* x    = (const float*)d_in[0];
    const int*   seg  = (const int*)  d_in[1];
    const float* p1w0 = (const float*)d_in[2];
    const float* p1b0 = (const float*)d_in[3];
    const float* p1w1 = (const float*)d_in[4];
    const float* p1b1 = (const float*)d_in[5];
    const float* r1w0 = (const float*)d_in[6];
    const float* r1b0 = (const float*)d_in[7];
    const float* r1w1 = (const float*)d_in[8];
    const float* r1b1 = (const float*)d_in[9];
    const float* o1w  = (const float*)d_in[10];
    const float* o1b  = (const float*)d_in[11];
    const float* p2w0 = (const float*)d_in[12];
    const float* p2b0 = (const float*)d_in[13];
    const float* p2w1 = (const float*)d_in[14];
    const float* p2b1 = (const float*)d_in[15];
    const float* r2w0 = (const float*)d_in[16];
    const float* r2b0 = (const float*)d_in[17];
    const float* r2w1 = (const float*)d_in[18];
    const float* r2b1 = (const float*)d_in[19];
    const float* o2w  = (const float*)d_in[20];
    const float* o2b  = (const float*)d_in[21];
    const int n = in_sizes[0];

    void* zp = nullptr;
    cudaGetSymbolAddress(&zp, g_zero);
    cudaMemsetAsync(zp, 0, sizeof(float) * (2 * E_NUM + D + E_NUM * D));

    k_stage1<<<S1_BLOCKS, 256>>>(x, seg, n, p1w0, p1b0, p1w1, p1b1, r1w0);
    k_events_final<<<EV_BLOCKS, 128>>>(r1w0, r1b0, r1w1, r1b1, o1w, o1b,
                                       p2w0, p2b0, p2w1, p2b1,
                                       r2w0, r2b0, r2w1, r2b1,
                                       o2w, o2b, (float*)d_out);
}